// round 1
// baseline (speedup 1.0000x reference)
#include <cuda_runtime.h>
#include <mma.h>

using namespace nvcuda;

// Problem constants (fixed by the reference)
#define BB 2
#define SS 2048
#define HH 1024
#define FF 4096
#define EE 8
#define KK 2
#define NT (BB*SS)          // 4096 tokens
#define NENT (KK*NT)        // 8192 (token,k) entries
#define TILE_M 128
#define MAX_TILES (NENT/TILE_M + EE)   // 72 row tiles max (tile-aligned expert groups)
#define CAPROWS (MAX_TILES*TILE_M)     // 9216 rows capacity

// GEMM tiling
#define BK 32
#define LDA 40     // 128 x 40 f32 A tile (padded, float4-aligned rows)
#define LDB 136    // 32 x 136 f32 B tile
#define LDE 68     // epilogue staging ld (128 x 68, multiple of 4)

// ---------------- scratch (static device globals; no runtime allocation) ----
__device__ int   g_count[EE];
__device__ int   g_cursor[EE];
__device__ int   g_tile_expert[MAX_TILES];
__device__ int   g_tile_row0[MAX_TILES];
__device__ int   g_row_src[CAPROWS];        // token index or -1 (padding)
__device__ float g_row_prob[CAPROWS];
__device__ float g_hbuf[(size_t)CAPROWS * FF];   // GEMM1 output (post-gelu)

// ---------------- routing ---------------------------------------------------
__global__ void route_init() {
    int i = blockIdx.x * blockDim.x + threadIdx.x;
    if (i < EE) { g_count[i] = 0; }
    if (i < CAPROWS) { g_row_src[i] = -1; g_row_prob[i] = 0.f; }
}

__global__ void route_count(const int* __restrict__ sel) {
    int i = blockIdx.x * blockDim.x + threadIdx.x;
    if (i < NENT) atomicAdd(&g_count[sel[i] & (EE - 1)], 1);
}

__global__ void route_offsets() {
    if (threadIdx.x == 0 && blockIdx.x == 0) {
        int start = 0, tl = 0;
        for (int e = 0; e < EE; e++) {
            int cnt = g_count[e];
            int nt = (cnt + TILE_M - 1) / TILE_M;
            g_cursor[e] = start;                 // scatter write base
            for (int j = 0; j < nt; j++) {
                g_tile_expert[tl] = e;
                g_tile_row0[tl] = start + j * TILE_M;
                tl++;
            }
            start += nt * TILE_M;
        }
        for (; tl < MAX_TILES; tl++) g_tile_expert[tl] = -1;
    }
}

__global__ void route_scatter(const int* __restrict__ sel,
                              const float* __restrict__ probs) {
    int i = blockIdx.x * blockDim.x + threadIdx.x;
    if (i >= NENT) return;
    int e = sel[i] & (EE - 1);
    int pos = atomicAdd(&g_cursor[e], 1);
    g_row_src[pos]  = i % NT;   // leading axis is K: token = i mod (B*S)
    g_row_prob[pos] = probs[i];
}

__global__ void zero_out(float* __restrict__ out) {
    int i = blockIdx.x * blockDim.x + threadIdx.x;
    if (i < NT * HH / 4) {
        float4 z = make_float4(0.f, 0.f, 0.f, 0.f);
        reinterpret_cast<float4*>(out)[i] = z;
    }
}

// ---------------- GEMM1: Hbuf = gelu(gather(x) @ W1[e] + b1[e]) -------------
__global__ __launch_bounds__(256)
void gemm1(const float* __restrict__ x,
           const float* __restrict__ w1,
           const float* __restrict__ b1) {
    int tile = blockIdx.x;
    int e = g_tile_expert[tile];
    if (e < 0) return;
    int row0 = g_tile_row0[tile];
    int n0 = blockIdx.y * 128;

    __shared__ float smem[128 * LDA + BK * LDB];   // 9472 floats = 37 KB
    float* sA = smem;
    float* sB = smem + 128 * LDA;
    float* sE = smem;                               // epilogue aliases

    int tid = threadIdx.x;
    int warpId = tid >> 5;
    int wm = warpId >> 2;   // 0..1 (M half)
    int wn = warpId & 3;    // 0..3 (N quarter)

    wmma::fragment<wmma::accumulator, 16, 16, 8, float> acc[4][2];
    #pragma unroll
    for (int i = 0; i < 4; i++)
        #pragma unroll
        for (int j = 0; j < 2; j++)
            wmma::fill_fragment(acc[i][j], 0.f);

    const float* wB = w1 + (size_t)e * HH * FF;

    for (int ko = 0; ko < HH; ko += BK) {
        // A tile: 128 rows x 32 cols, gathered from x via row_src
        #pragma unroll
        for (int i = 0; i < 4; i++) {
            int r = (tid >> 3) + i * 32;
            int c = (tid & 7) * 4;
            int src = g_row_src[row0 + r];
            float4 v = make_float4(0.f, 0.f, 0.f, 0.f);
            if (src >= 0)
                v = *reinterpret_cast<const float4*>(x + (size_t)src * HH + ko + c);
            *reinterpret_cast<float4*>(sA + r * LDA + c) = v;
        }
        // B tile: 32 rows x 128 cols of W1[e]
        #pragma unroll
        for (int i = 0; i < 4; i++) {
            int r = (tid >> 5) + i * 8;
            int c = (tid & 31) * 4;
            float4 v = *reinterpret_cast<const float4*>(wB + (size_t)(ko + r) * FF + n0 + c);
            *reinterpret_cast<float4*>(sB + r * LDB + c) = v;
        }
        __syncthreads();

        #pragma unroll
        for (int kk = 0; kk < BK; kk += 8) {
            wmma::fragment<wmma::matrix_a, 16, 16, 8, wmma::precision::tf32, wmma::row_major> af[4];
            wmma::fragment<wmma::matrix_b, 16, 16, 8, wmma::precision::tf32, wmma::row_major> bf[2];
            #pragma unroll
            for (int i = 0; i < 4; i++) {
                wmma::load_matrix_sync(af[i], sA + (wm * 64 + i * 16) * LDA + kk, LDA);
                #pragma unroll
                for (int t = 0; t < af[i].num_elements; t++)
                    af[i].x[t] = wmma::__float_to_tf32(af[i].x[t]);
            }
            #pragma unroll
            for (int j = 0; j < 2; j++) {
                wmma::load_matrix_sync(bf[j], sB + kk * LDB + wn * 32 + j * 16, LDB);
                #pragma unroll
                for (int t = 0; t < bf[j].num_elements; t++)
                    bf[j].x[t] = wmma::__float_to_tf32(bf[j].x[t]);
            }
            #pragma unroll
            for (int i = 0; i < 4; i++)
                #pragma unroll
                for (int j = 0; j < 2; j++)
                    wmma::mma_sync(acc[i][j], af[i], bf[j], acc[i][j]);
        }
        __syncthreads();
    }

    // Epilogue: bias + gelu(tanh approx), staged through smem in two 128x64 halves
    for (int h = 0; h < 2; h++) {
        if ((wn >> 1) == h) {
            #pragma unroll
            for (int i = 0; i < 4; i++)
                #pragma unroll
                for (int j = 0; j < 2; j++)
                    wmma::store_matrix_sync(
                        sE + (wm * 64 + i * 16) * LDE + (wn & 1) * 32 + j * 16,
                        acc[i][j], LDE, wmma::mem_row_major);
        }
        __syncthreads();
        #pragma unroll 4
        for (int it = 0; it < 32; it++) {
            int lin = tid + 256 * it;
            int r = lin >> 6, c = lin & 63;
            int n = n0 + h * 64 + c;
            float v = sE[r * LDE + c] + b1[e * FF + n];
            float u = 0.7978845608028654f * (v + 0.044715f * v * v * v);
            float g = 0.5f * v * (1.0f + tanhf(u));
            g_hbuf[(size_t)(row0 + r) * FF + n] = g;
        }
        __syncthreads();
    }
}

// ---------------- GEMM2: out += prob * (Hbuf @ W2[e] + b2[e]) ---------------
__global__ __launch_bounds__(256)
void gemm2(const float* __restrict__ w2,
           const float* __restrict__ b2,
           float* __restrict__ out) {
    int tile = blockIdx.x;
    int e = g_tile_expert[tile];
    if (e < 0) return;
    int row0 = g_tile_row0[tile];
    int n0 = blockIdx.y * 128;

    __shared__ float smem[128 * LDA + BK * LDB];
    float* sA = smem;
    float* sB = smem + 128 * LDA;
    float* sE = smem;

    int tid = threadIdx.x;
    int warpId = tid >> 5;
    int wm = warpId >> 2;
    int wn = warpId & 3;

    wmma::fragment<wmma::accumulator, 16, 16, 8, float> acc[4][2];
    #pragma unroll
    for (int i = 0; i < 4; i++)
        #pragma unroll
        for (int j = 0; j < 2; j++)
            wmma::fill_fragment(acc[i][j], 0.f);

    const float* wB = w2 + (size_t)e * FF * HH;

    for (int ko = 0; ko < FF; ko += BK) {
        #pragma unroll
        for (int i = 0; i < 4; i++) {
            int r = (tid >> 3) + i * 32;
            int c = (tid & 7) * 4;
            float4 v = *reinterpret_cast<const float4*>(
                g_hbuf + (size_t)(row0 + r) * FF + ko + c);
            *reinterpret_cast<float4*>(sA + r * LDA + c) = v;
        }
        #pragma unroll
        for (int i = 0; i < 4; i++) {
            int r = (tid >> 5) + i * 8;
            int c = (tid & 31) * 4;
            float4 v = *reinterpret_cast<const float4*>(wB + (size_t)(ko + r) * HH + n0 + c);
            *reinterpret_cast<float4*>(sB + r * LDB + c) = v;
        }
        __syncthreads();

        #pragma unroll
        for (int kk = 0; kk < BK; kk += 8) {
            wmma::fragment<wmma::matrix_a, 16, 16, 8, wmma::precision::tf32, wmma::row_major> af[4];
            wmma::fragment<wmma::matrix_b, 16, 16, 8, wmma::precision::tf32, wmma::row_major> bf[2];
            #pragma unroll
            for (int i = 0; i < 4; i++) {
                wmma::load_matrix_sync(af[i], sA + (wm * 64 + i * 16) * LDA + kk, LDA);
                #pragma unroll
                for (int t = 0; t < af[i].num_elements; t++)
                    af[i].x[t] = wmma::__float_to_tf32(af[i].x[t]);
            }
            #pragma unroll
            for (int j = 0; j < 2; j++) {
                wmma::load_matrix_sync(bf[j], sB + kk * LDB + wn * 32 + j * 16, LDB);
                #pragma unroll
                for (int t = 0; t < bf[j].num_elements; t++)
                    bf[j].x[t] = wmma::__float_to_tf32(bf[j].x[t]);
            }
            #pragma unroll
            for (int i = 0; i < 4; i++)
                #pragma unroll
                for (int j = 0; j < 2; j++)
                    wmma::mma_sync(acc[i][j], af[i], bf[j], acc[i][j]);
        }
        __syncthreads();
    }

    for (int h = 0; h < 2; h++) {
        if ((wn >> 1) == h) {
            #pragma unroll
            for (int i = 0; i < 4; i++)
                #pragma unroll
                for (int j = 0; j < 2; j++)
                    wmma::store_matrix_sync(
                        sE + (wm * 64 + i * 16) * LDE + (wn & 1) * 32 + j * 16,
                        acc[i][j], LDE, wmma::mem_row_major);
        }
        __syncthreads();
        #pragma unroll 4
        for (int it = 0; it < 32; it++) {
            int lin = tid + 256 * it;
            int r = lin >> 6, c = lin & 63;
            int grow = row0 + r;
            int src = g_row_src[grow];
            if (src >= 0) {
                int n = n0 + h * 64 + c;
                float v = sE[r * LDE + c] + b2[e * HH + n];
                atomicAdd(out + (size_t)src * HH + n, g_row_prob[grow] * v);
            }
        }
        __syncthreads();
    }
}

// ---------------- launch -----------------------------------------------------
extern "C" void kernel_launch(void* const* d_in, const int* in_sizes, int n_in,
                              void* d_out, int out_size) {
    (void)in_sizes; (void)n_in; (void)out_size;
    const float* x     = (const float*)d_in[0];
    const float* probs = (const float*)d_in[1];
    const int*   sel   = (const int*)  d_in[2];
    const float* w1    = (const float*)d_in[3];
    const float* b1    = (const float*)d_in[4];
    const float* w2    = (const float*)d_in[5];
    const float* b2    = (const float*)d_in[6];
    float* out = (float*)d_out;

    route_init<<<(CAPROWS + 255) / 256, 256>>>();
    route_count<<<NENT / 256, 256>>>(sel);
    route_offsets<<<1, 32>>>();
    route_scatter<<<NENT / 256, 256>>>(sel, probs);
    zero_out<<<(NT * HH / 4) / 256, 256>>>(out);

    dim3 g1(MAX_TILES, FF / 128);
    gemm1<<<g1, 256>>>(x, w1, b1);
    dim3 g2(MAX_TILES, HH / 128);
    gemm2<<<g2, 256>>>(w2, b2, out);
}

// round 2
// speedup vs baseline: 1.2957x; 1.2957x over previous
#include <cuda_runtime.h>
#include <mma.h>

using namespace nvcuda;

// Problem constants (fixed by the reference)
#define BB 2
#define SS 2048
#define HH 1024
#define FF 4096
#define EE 8
#define KK 2
#define NT (BB*SS)          // 4096 tokens
#define NENT (KK*NT)        // 8192 (token,k) entries
#define TILE_M 128
#define MAX_TILES (NENT/TILE_M + EE)   // 72 row tiles max
#define CAPROWS (MAX_TILES*TILE_M)     // 9216 rows capacity

// GEMM tiling
#define BK 32
#define NSTAGE 3
#define LDA 36                      // padded A row (floats), 16B aligned
#define LDB 132                     // padded B row (floats)
#define STAGE_A (128*LDA)           // 4608 floats
#define STAGE_B (BK*LDB)            // 4224 floats
#define STAGE_F (STAGE_A+STAGE_B)   // 8832 floats per stage
#define SMEM_BYTES (NSTAGE*STAGE_F*4)   // 105984 B
#define LDE 68                      // epilogue staging row

// ---------------- scratch ----------------------------------------------------
__device__ int   g_count[EE];
__device__ int   g_cursor[EE];
__device__ int   g_tile_expert[MAX_TILES];
__device__ int   g_tile_row0[MAX_TILES];
__device__ int   g_row_src[CAPROWS];
__device__ float g_row_prob[CAPROWS];
__device__ float g_hbuf[(size_t)CAPROWS * FF];

// ---------------- routing ----------------------------------------------------
__global__ void route_init() {
    int i = blockIdx.x * blockDim.x + threadIdx.x;
    if (i < EE) g_count[i] = 0;
    if (i < CAPROWS) { g_row_src[i] = -1; g_row_prob[i] = 0.f; }
}

__global__ void route_count(const int* __restrict__ sel) {
    int i = blockIdx.x * blockDim.x + threadIdx.x;
    if (i < NENT) atomicAdd(&g_count[sel[i] & (EE - 1)], 1);
}

__global__ void route_offsets() {
    if (threadIdx.x == 0 && blockIdx.x == 0) {
        int start = 0, tl = 0;
        for (int e = 0; e < EE; e++) {
            int cnt = g_count[e];
            int nt = (cnt + TILE_M - 1) / TILE_M;
            g_cursor[e] = start;
            for (int j = 0; j < nt; j++) {
                g_tile_expert[tl] = e;
                g_tile_row0[tl] = start + j * TILE_M;
                tl++;
            }
            start += nt * TILE_M;
        }
        for (; tl < MAX_TILES; tl++) g_tile_expert[tl] = -1;
    }
}

__global__ void route_scatter(const int* __restrict__ sel,
                              const float* __restrict__ probs) {
    int i = blockIdx.x * blockDim.x + threadIdx.x;
    if (i >= NENT) return;
    int e = sel[i] & (EE - 1);
    int pos = atomicAdd(&g_cursor[e], 1);
    g_row_src[pos]  = i % NT;
    g_row_prob[pos] = probs[i];
}

__global__ void zero_out(float* __restrict__ out) {
    int i = blockIdx.x * blockDim.x + threadIdx.x;
    if (i < NT * HH / 4) {
        float4 z = make_float4(0.f, 0.f, 0.f, 0.f);
        reinterpret_cast<float4*>(out)[i] = z;
    }
}

// ---------------- cp.async helpers -------------------------------------------
__device__ __forceinline__ void cp_async16(float* smem_dst, const float* gsrc, int src_bytes) {
    unsigned saddr = (unsigned)__cvta_generic_to_shared(smem_dst);
    asm volatile("cp.async.cg.shared.global [%0], [%1], 16, %2;\n"
                 :: "r"(saddr), "l"(gsrc), "r"(src_bytes));
}
__device__ __forceinline__ void cp_commit() {
    asm volatile("cp.async.commit_group;\n");
}
template<int N>
__device__ __forceinline__ void cp_wait() {
    asm volatile("cp.async.wait_group %0;\n" :: "n"(N));
}

// ---------------- fused pipelined GEMM ---------------------------------------
// G1:  hbuf = gelu(gather(x) @ W1[e] + b1[e])       (K=HH, N=FF)
// !G1: out += prob * (hbuf @ W2[e] + b2[e])         (K=FF, N=HH)
template<bool G1>
__global__ __launch_bounds__(256, 2)
void gemm_kernel(const float* __restrict__ Asrc,   // x (G1) / unused (G2)
                 const float* __restrict__ W,
                 const float* __restrict__ bias,
                 float* __restrict__ out)          // unused (G1) / out (G2)
{
    const int tile = blockIdx.y;
    const int e = g_tile_expert[tile];
    if (e < 0) return;
    const int row0 = g_tile_row0[tile];
    const int n0 = blockIdx.x * 128;

    const int KDIM = G1 ? HH : FF;
    const int NDIM = G1 ? FF : HH;
    const int NIT  = KDIM / BK;

    extern __shared__ float dynsm[];

    const int tid = threadIdx.x;
    const int warpId = tid >> 5;
    const int wm = warpId >> 2;   // 0..1
    const int wn = warpId & 3;    // 0..3

    // ---- per-thread load descriptors (hoisted out of K loop) ----
    const float* aPtr[4];
    int aBytes[4];
    int aOff[4];
    {
        int c4 = tid & 7;
        #pragma unroll
        for (int i = 0; i < 4; i++) {
            int r = (tid >> 3) + i * 32;
            aOff[i] = r * LDA + c4 * 4;
            if (G1) {
                int src = g_row_src[row0 + r];
                aPtr[i] = Asrc + (size_t)(src >= 0 ? src : 0) * HH + c4 * 4;
                aBytes[i] = (src >= 0) ? 16 : 0;
            } else {
                aPtr[i] = g_hbuf + (size_t)(row0 + r) * FF + c4 * 4;
                aBytes[i] = 16;
            }
        }
    }
    const float* bPtr[4];
    int bOff[4];
    {
        const float* wB = W + (size_t)e * HH * FF;
        int c4 = tid & 31;
        #pragma unroll
        for (int i = 0; i < 4; i++) {
            int r = (tid >> 5) + i * 8;
            bOff[i] = r * LDB + c4 * 4;
            bPtr[i] = wB + (size_t)r * NDIM + n0 + c4 * 4;
        }
    }

    auto issue = [&](int s, int ko) {
        float* base = dynsm + s * STAGE_F;
        #pragma unroll
        for (int i = 0; i < 4; i++)
            cp_async16(base + aOff[i], aPtr[i] + ko, aBytes[i]);
        float* bb = base + STAGE_A;
        #pragma unroll
        for (int i = 0; i < 4; i++)
            cp_async16(bb + bOff[i], bPtr[i] + (size_t)ko * NDIM, 16);
    };

    wmma::fragment<wmma::accumulator, 16, 16, 8, float> acc[4][2];
    #pragma unroll
    for (int i = 0; i < 4; i++)
        #pragma unroll
        for (int j = 0; j < 2; j++)
            wmma::fill_fragment(acc[i][j], 0.f);

    // ---- prologue: fill NSTAGE-1 stages ----
    #pragma unroll
    for (int s = 0; s < NSTAGE - 1; s++) { issue(s, s * BK); cp_commit(); }

    // ---- main loop ----
    for (int it = 0; it < NIT; ++it) {
        int sb = it % NSTAGE;
        int pre = it + NSTAGE - 1;
        if (pre < NIT) issue(pre % NSTAGE, pre * BK);
        cp_commit();
        cp_wait<NSTAGE - 2>();
        __syncthreads();

        const float* sA = dynsm + sb * STAGE_F;
        const float* sB = sA + STAGE_A;
        #pragma unroll
        for (int kk = 0; kk < BK; kk += 8) {
            wmma::fragment<wmma::matrix_a, 16, 16, 8, wmma::precision::tf32, wmma::row_major> af[4];
            wmma::fragment<wmma::matrix_b, 16, 16, 8, wmma::precision::tf32, wmma::row_major> bf[2];
            #pragma unroll
            for (int i = 0; i < 4; i++) {
                wmma::load_matrix_sync(af[i], sA + (wm * 64 + i * 16) * LDA + kk, LDA);
                #pragma unroll
                for (int t = 0; t < af[i].num_elements; t++)
                    af[i].x[t] = wmma::__float_to_tf32(af[i].x[t]);
            }
            #pragma unroll
            for (int j = 0; j < 2; j++) {
                wmma::load_matrix_sync(bf[j], sB + kk * LDB + wn * 32 + j * 16, LDB);
                #pragma unroll
                for (int t = 0; t < bf[j].num_elements; t++)
                    bf[j].x[t] = wmma::__float_to_tf32(bf[j].x[t]);
            }
            #pragma unroll
            for (int i = 0; i < 4; i++)
                #pragma unroll
                for (int j = 0; j < 2; j++)
                    wmma::mma_sync(acc[i][j], af[i], bf[j], acc[i][j]);
        }
        __syncthreads();
    }

    // ---- epilogue: stage accumulators through smem in two 128x64 halves ----
    float* sE = dynsm;
    for (int h = 0; h < 2; h++) {
        if ((wn >> 1) == h) {
            #pragma unroll
            for (int i = 0; i < 4; i++)
                #pragma unroll
                for (int j = 0; j < 2; j++)
                    wmma::store_matrix_sync(
                        sE + (wm * 64 + i * 16) * LDE + (wn & 1) * 32 + j * 16,
                        acc[i][j], LDE, wmma::mem_row_major);
        }
        __syncthreads();
        #pragma unroll 4
        for (int it = 0; it < 32; it++) {
            int lin = tid + 256 * it;
            int r = lin >> 6, c = lin & 63;
            int n = n0 + h * 64 + c;
            if (G1) {
                float v = sE[r * LDE + c] + bias[e * FF + n];
                float u = 0.7978845608028654f * (v + 0.044715f * v * v * v);
                float g = 0.5f * v * (1.0f + tanhf(u));
                g_hbuf[(size_t)(row0 + r) * FF + n] = g;
            } else {
                int grow = row0 + r;
                int src = g_row_src[grow];
                if (src >= 0) {
                    float v = sE[r * LDE + c] + bias[e * HH + n];
                    atomicAdd(out + (size_t)src * HH + n, g_row_prob[grow] * v);
                }
            }
        }
        __syncthreads();
    }
}

// ---------------- launch ------------------------------------------------------
extern "C" void kernel_launch(void* const* d_in, const int* in_sizes, int n_in,
                              void* d_out, int out_size) {
    (void)in_sizes; (void)n_in; (void)out_size;
    const float* x     = (const float*)d_in[0];
    const float* probs = (const float*)d_in[1];
    const int*   sel   = (const int*)  d_in[2];
    const float* w1    = (const float*)d_in[3];
    const float* b1    = (const float*)d_in[4];
    const float* w2    = (const float*)d_in[5];
    const float* b2    = (const float*)d_in[6];
    float* out = (float*)d_out;

    cudaFuncSetAttribute(gemm_kernel<true>,
                         cudaFuncAttributeMaxDynamicSharedMemorySize, SMEM_BYTES);
    cudaFuncSetAttribute(gemm_kernel<false>,
                         cudaFuncAttributeMaxDynamicSharedMemorySize, SMEM_BYTES);

    route_init<<<(CAPROWS + 255) / 256, 256>>>();
    route_count<<<NENT / 256, 256>>>(sel);
    route_offsets<<<1, 32>>>();
    route_scatter<<<NENT / 256, 256>>>(sel, probs);
    zero_out<<<(NT * HH / 4) / 256, 256>>>(out);

    // x = n0 (fast-varying): consecutive blocks share the A-slab; per-expert
    // weight slabs stay L2-resident across the tile sweep.
    dim3 g1(FF / 128, MAX_TILES);
    gemm_kernel<true><<<g1, 256, SMEM_BYTES>>>(x, w1, b1, nullptr);
    dim3 g2(HH / 128, MAX_TILES);
    gemm_kernel<false><<<g2, 256, SMEM_BYTES>>>(nullptr, w2, b2, out);
}